// round 1
// baseline (speedup 1.0000x reference)
#include <cuda_runtime.h>
#include <math.h>

#define N_NODE 80000
#define N_NET  20000
#define NEDGE  150000
#define HD     32      // node/net hidden + out dims
#define HE     16      // pin/edge feature dims
#define WROWS  (HD*HD) // 1024 rows of the edge-MLP weight
#define WSZ    (WROWS*HE)

// ---- scratch (device globals; no allocation allowed) ----
__device__ float g_deg_out[N_NODE];
__device__ float g_deg_in [N_NET];
__device__ float g_deg_p  [N_NODE];
__device__ float g_deg_n  [N_NODE];
__device__ float g_agg    [N_NET * HD];
__device__ float g_accp   [N_NODE * HD];
__device__ float g_accn   [N_NODE * HD];

// ---------------------------------------------------------------------------
__global__ void k_zero() {
    int stride = gridDim.x * blockDim.x;
    int i0 = blockIdx.x * blockDim.x + threadIdx.x;
    for (int j = i0; j < N_NODE; j += stride) {
        g_deg_out[j] = 0.f; g_deg_p[j] = 0.f; g_deg_n[j] = 0.f;
    }
    for (int j = i0; j < N_NET; j += stride) g_deg_in[j] = 0.f;
    for (int j = i0; j < N_NET * HD; j += stride) g_agg[j] = 0.f;
    for (int j = i0; j < N_NODE * HD; j += stride) {
        g_accp[j] = 0.f; g_accn[j] = 0.f;
    }
}

// ---------------------------------------------------------------------------
__global__ void k_deg(const int* __restrict__ ps, const int* __restrict__ pd,
                      const int* __restrict__ pnd, const int* __restrict__ nrd) {
    int e = blockIdx.x * blockDim.x + threadIdx.x;
    if (e >= NEDGE) return;
    atomicAdd(&g_deg_out[ps[e]],  1.f);
    atomicAdd(&g_deg_in [pd[e]],  1.f);
    atomicAdd(&g_deg_p  [pnd[e]], 1.f);
    atomicAdd(&g_deg_n  [nrd[e]], 1.f);
}

// ---------------------------------------------------------------------------
// pins relation aggregation: agg[dst] += node_feat[src] * rsqrt(max(deg_out[src],1))
__global__ void k_pins(const float* __restrict__ nodef,
                       const int* __restrict__ src, const int* __restrict__ dst) {
    int t = blockIdx.x * blockDim.x + threadIdx.x;
    if (t >= NEDGE * HD) return;
    int e = t >> 5, c = t & 31;
    int s = src[e];
    float nrm = rsqrtf(fmaxf(g_deg_out[s], 1.f));
    atomicAdd(&g_agg[(size_t)dst[e] * HD + c], nodef[(size_t)s * HD + c] * nrm);
}

// ---------------------------------------------------------------------------
// net_out[n,o] = (sum_d agg[n,d] * gc_w[d,o]) * rsqrt(max(deg_in,1)) + gc_b[o]
__global__ void k_netout(const float* __restrict__ gcw, const float* __restrict__ gcb,
                         float* __restrict__ out) {
    int t = blockIdx.x * blockDim.x + threadIdx.x;
    if (t >= N_NET * HD) return;
    int n = t >> 5, o = t & 31;
    float nrm = rsqrtf(fmaxf(g_deg_in[n], 1.f));
    float a = 0.f;
    #pragma unroll
    for (int d = 0; d < HD; d++)
        a = fmaf(g_agg[n * HD + d], gcw[d * HD + o], a);
    out[(size_t)N_NODE * HD + t] = a * nrm + gcb[o];
}

// ---------------------------------------------------------------------------
// NNConv edge kernel. One thread = one edge. W (1024x16) + bias in shared,
// indexed identically across lanes -> pure broadcast LDS. Per-edge src feature
// (32) and edge feature (16) live in registers.
// msg[o] = sum_i nf[i] * ( b[i*32+o] + sum_k pf[k]*W[i*32+o, k] )
__global__ void k_nnconv(const float* __restrict__ srcfeat,
                         const float* __restrict__ efeat,
                         const float* __restrict__ w, const float* __restrict__ b,
                         const int* __restrict__ src, const int* __restrict__ dst,
                         float* __restrict__ acc) {
    extern __shared__ float sm[];
    float* ws = sm;          // 1024*16
    float* bs = sm + WSZ;    // 1024
    for (int i = threadIdx.x; i < WSZ; i += blockDim.x) ws[i] = w[i];
    for (int i = threadIdx.x; i < WROWS; i += blockDim.x) bs[i] = b[i];
    __syncthreads();

    int e = blockIdx.x * blockDim.x + threadIdx.x;
    if (e >= NEDGE) return;
    int s = src[e];
    int d = dst[e];

    float nf[HD];
    {
        const float4* r = reinterpret_cast<const float4*>(srcfeat + (size_t)s * HD);
        #pragma unroll
        for (int i = 0; i < HD / 4; i++) {
            float4 v = r[i];
            nf[4*i] = v.x; nf[4*i+1] = v.y; nf[4*i+2] = v.z; nf[4*i+3] = v.w;
        }
    }
    float pf[HE];
    {
        const float4* r = reinterpret_cast<const float4*>(efeat + (size_t)e * HE);
        #pragma unroll
        for (int k = 0; k < HE / 4; k++) {
            float4 v = r[k];
            pf[4*k] = v.x; pf[4*k+1] = v.y; pf[4*k+2] = v.z; pf[4*k+3] = v.w;
        }
    }

    #pragma unroll 1
    for (int o = 0; o < HD; o++) {
        float acc_o = 0.f;
        #pragma unroll
        for (int i = 0; i < HD; i++) {
            const float* wr = ws + (i * HD + o) * HE;   // lane-uniform address
            float t = bs[i * HD + o];
            #pragma unroll
            for (int k = 0; k < HE; k++)
                t = fmaf(pf[k], wr[k], t);
            acc_o = fmaf(nf[i], t, acc_o);
        }
        atomicAdd(&acc[(size_t)d * HD + o], acc_o);
    }
}

// ---------------------------------------------------------------------------
__global__ void k_final(const float* __restrict__ pb, const float* __restrict__ nb,
                        float* __restrict__ out) {
    int t = blockIdx.x * blockDim.x + threadIdx.x;
    if (t >= N_NODE * HD) return;
    int n = t >> 5, o = t & 31;
    float p = g_accp[t] / fmaxf(g_deg_p[n], 1.f) + pb[o];
    float q = g_accn[t] / fmaxf(g_deg_n[n], 1.f) + nb[o];
    out[t] = fmaxf(p, q);
}

// ---------------------------------------------------------------------------
extern "C" void kernel_launch(void* const* d_in, const int* in_sizes, int n_in,
                              void* d_out, int out_size) {
    const float* node_feat = (const float*)d_in[0];
    const float* net_feat  = (const float*)d_in[1];
    const float* pin_feat  = (const float*)d_in[2];
    const float* edge_feat = (const float*)d_in[3];
    const float* topo_w    = (const float*)d_in[4];
    const float* topo_b    = (const float*)d_in[5];
    const float* geom_w    = (const float*)d_in[6];
    const float* geom_b    = (const float*)d_in[7];
    const float* gc_w      = (const float*)d_in[8];
    const float* gc_b      = (const float*)d_in[9];
    const float* pinned_b  = (const float*)d_in[10];
    const float* near_b    = (const float*)d_in[11];
    const int* pins_src    = (const int*)d_in[12];
    const int* pins_dst    = (const int*)d_in[13];
    const int* pinned_src  = (const int*)d_in[14];
    const int* pinned_dst  = (const int*)d_in[15];
    const int* near_src    = (const int*)d_in[16];
    const int* near_dst    = (const int*)d_in[17];
    float* out = (float*)d_out;

    const int smem = (WSZ + WROWS) * (int)sizeof(float);   // 69632 B
    cudaFuncSetAttribute(k_nnconv, cudaFuncAttributeMaxDynamicSharedMemorySize, smem);

    float *accp_ptr = nullptr, *accn_ptr = nullptr;
    cudaGetSymbolAddress((void**)&accp_ptr, g_accp);
    cudaGetSymbolAddress((void**)&accn_ptr, g_accn);

    k_zero<<<512, 256>>>();
    k_deg<<<(NEDGE + 255) / 256, 256>>>(pins_src, pins_dst, pinned_dst, near_dst);
    k_pins<<<(NEDGE * HD + 255) / 256, 256>>>(node_feat, pins_src, pins_dst);
    k_netout<<<(N_NET * HD + 255) / 256, 256>>>(gc_w, gc_b, out);

    int nb = (NEDGE + 255) / 256;
    k_nnconv<<<nb, 256, smem>>>(net_feat,  pin_feat,  topo_w, topo_b,
                                pinned_src, pinned_dst, accp_ptr);
    k_nnconv<<<nb, 256, smem>>>(node_feat, edge_feat, geom_w, geom_b,
                                near_src,  near_dst,  accn_ptr);

    k_final<<<(N_NODE * HD + 255) / 256, 256>>>(pinned_b, near_b, out);
}

// round 2
// speedup vs baseline: 1.3536x; 1.3536x over previous
#include <cuda_runtime.h>
#include <math.h>

#define N_NODE 80000
#define N_NET  20000
#define NEDGE  150000
#define HD     32      // node/net hidden + out dims
#define HE     16      // pin/edge feature dims
#define WROWS  (HD*HD) // 1024 rows of the edge-MLP weight
#define WSZ    (WROWS*HE)

typedef unsigned long long u64;

// ---- packed f32x2 helpers (FFMA2: sm_103a, PTX-only) ----
__device__ __forceinline__ u64 pack2(float lo, float hi) {
    u64 r; asm("mov.b64 %0, {%1, %2};" : "=l"(r) : "f"(lo), "f"(hi)); return r;
}
__device__ __forceinline__ u64 fma2(u64 a, u64 b, u64 c) {
    u64 d; asm("fma.rn.f32x2 %0, %1, %2, %3;" : "=l"(d) : "l"(a), "l"(b), "l"(c)); return d;
}
__device__ __forceinline__ u64 mul2(u64 a, u64 b) {
    u64 d; asm("mul.rn.f32x2 %0, %1, %2;" : "=l"(d) : "l"(a), "l"(b)); return d;
}
__device__ __forceinline__ void unpack2(u64 v, float& lo, float& hi) {
    asm("mov.b64 {%0, %1}, %2;" : "=f"(lo), "=f"(hi) : "l"(v));
}

// ---- scratch (device globals; no allocation allowed) ----
__device__ float g_deg_out[N_NODE];
__device__ float g_deg_in [N_NET];
__device__ float g_deg_p  [N_NODE];
__device__ float g_deg_n  [N_NODE];
__device__ float g_agg    [N_NET * HD];
__device__ float g_accp   [N_NODE * HD];
__device__ float g_accn   [N_NODE * HD];

// ---------------------------------------------------------------------------
__global__ void k_zero() {
    int stride = gridDim.x * blockDim.x;
    int i0 = blockIdx.x * blockDim.x + threadIdx.x;
    for (int j = i0; j < N_NODE; j += stride) {
        g_deg_out[j] = 0.f; g_deg_p[j] = 0.f; g_deg_n[j] = 0.f;
    }
    for (int j = i0; j < N_NET; j += stride) g_deg_in[j] = 0.f;
    for (int j = i0; j < N_NET * HD; j += stride) g_agg[j] = 0.f;
    for (int j = i0; j < N_NODE * HD; j += stride) {
        g_accp[j] = 0.f; g_accn[j] = 0.f;
    }
}

// ---------------------------------------------------------------------------
__global__ void k_deg(const int* __restrict__ ps, const int* __restrict__ pd,
                      const int* __restrict__ pnd, const int* __restrict__ nrd) {
    int e = blockIdx.x * blockDim.x + threadIdx.x;
    if (e >= NEDGE) return;
    atomicAdd(&g_deg_out[ps[e]],  1.f);
    atomicAdd(&g_deg_in [pd[e]],  1.f);
    atomicAdd(&g_deg_p  [pnd[e]], 1.f);
    atomicAdd(&g_deg_n  [nrd[e]], 1.f);
}

// ---------------------------------------------------------------------------
__global__ void k_pins(const float* __restrict__ nodef,
                       const int* __restrict__ src, const int* __restrict__ dst) {
    int t = blockIdx.x * blockDim.x + threadIdx.x;
    if (t >= NEDGE * HD) return;
    int e = t >> 5, c = t & 31;
    int s = src[e];
    float nrm = rsqrtf(fmaxf(g_deg_out[s], 1.f));
    atomicAdd(&g_agg[(size_t)dst[e] * HD + c], nodef[(size_t)s * HD + c] * nrm);
}

// ---------------------------------------------------------------------------
__global__ void k_netout(const float* __restrict__ gcw, const float* __restrict__ gcb,
                         float* __restrict__ out) {
    int t = blockIdx.x * blockDim.x + threadIdx.x;
    if (t >= N_NET * HD) return;
    int n = t >> 5, o = t & 31;
    float nrm = rsqrtf(fmaxf(g_deg_in[n], 1.f));
    float a = 0.f;
    #pragma unroll
    for (int d = 0; d < HD; d++)
        a = fmaf(g_agg[n * HD + d], gcw[d * HD + o], a);
    out[(size_t)N_NODE * HD + t] = a * nrm + gcb[o];
}

// ---------------------------------------------------------------------------
// NNConv edge kernel, packed-f32x2 Z-formulation.
//   msg[o] = sum_{i,k} (nf[i]*pf[k]) * W[(i,o),k]  +  sum_i nf[i]*b[i,o]
// Output pairs (o, o+1) live in 16 f32x2 accumulators. Weight pairs come from
// a transposed smem copy wsT[(i*16+k)*32 + o] so {W[..,o],W[..,o+1]} is one
// broadcast LDS.64. Z duplicated into both lanes via pre-packed {x,x} dups.
__global__ void __launch_bounds__(256)
k_nnconv(const float* __restrict__ srcfeat,
         const float* __restrict__ efeat,
         const float* __restrict__ w, const float* __restrict__ b,
         const int* __restrict__ src, const int* __restrict__ dst,
         float* __restrict__ acc) {
    extern __shared__ float sm[];
    float* wsT = sm;          // 16384 floats: [i*16+k][o]
    float* bsS = sm + WSZ;    // 1024 floats:  [i][o]
    for (int idx = threadIdx.x; idx < WSZ; idx += blockDim.x) {
        int r = idx >> 4, k = idx & 15;    // source row-major: row r = i*32+o
        int i = r >> 5, o = r & 31;
        wsT[((i << 4) + k) * HD + o] = w[idx];
    }
    for (int idx = threadIdx.x; idx < WROWS; idx += blockDim.x) bsS[idx] = b[idx];
    __syncthreads();

    int e = blockIdx.x * blockDim.x + threadIdx.x;
    if (e >= NEDGE) return;
    int s = src[e];
    int d = dst[e];

    u64 nfd[HD];   // {nf[i], nf[i]}
    {
        const float4* r = reinterpret_cast<const float4*>(srcfeat + (size_t)s * HD);
        #pragma unroll
        for (int i = 0; i < HD / 4; i++) {
            float4 v = r[i];
            nfd[4*i+0] = pack2(v.x, v.x);
            nfd[4*i+1] = pack2(v.y, v.y);
            nfd[4*i+2] = pack2(v.z, v.z);
            nfd[4*i+3] = pack2(v.w, v.w);
        }
    }
    u64 pfd[HE];   // {pf[k], pf[k]}
    {
        const float4* r = reinterpret_cast<const float4*>(efeat + (size_t)e * HE);
        #pragma unroll
        for (int k = 0; k < HE / 4; k++) {
            float4 v = r[k];
            pfd[4*k+0] = pack2(v.x, v.x);
            pfd[4*k+1] = pack2(v.y, v.y);
            pfd[4*k+2] = pack2(v.z, v.z);
            pfd[4*k+3] = pack2(v.w, v.w);
        }
    }

    u64 msg2[HD / 2];
    #pragma unroll
    for (int op = 0; op < HD / 2; op++) msg2[op] = 0ull;   // packed {0,0}

    #pragma unroll 1
    for (int i = 0; i < HD; i++) {
        // bias: msg2[op] += nf[i] * {b[i,2op], b[i,2op+1]}
        const u64* b2 = reinterpret_cast<const u64*>(bsS + i * HD);
        #pragma unroll
        for (int op = 0; op < HD / 2; op++)
            msg2[op] = fma2(nfd[i], b2[op], msg2[op]);

        // Z row: z[k] = {nf[i]*pf[k]} duplicated
        u64 z[HE];
        #pragma unroll
        for (int k = 0; k < HE; k++) z[k] = mul2(nfd[i], pfd[k]);

        const u64* w2 = reinterpret_cast<const u64*>(wsT + i * (HE * HD));
        #pragma unroll
        for (int k = 0; k < HE; k++) {
            #pragma unroll
            for (int op = 0; op < HD / 2; op++)
                msg2[op] = fma2(z[k], w2[k * (HD / 2) + op], msg2[op]);
        }
    }

    float* ap = acc + (size_t)d * HD;
    #pragma unroll
    for (int op = 0; op < HD / 2; op++) {
        float lo, hi; unpack2(msg2[op], lo, hi);
        atomicAdd(ap + 2*op + 0, lo);
        atomicAdd(ap + 2*op + 1, hi);
    }
}

// ---------------------------------------------------------------------------
__global__ void k_final(const float* __restrict__ pb, const float* __restrict__ nb,
                        float* __restrict__ out) {
    int t = blockIdx.x * blockDim.x + threadIdx.x;
    if (t >= N_NODE * HD) return;
    int n = t >> 5, o = t & 31;
    float p = g_accp[t] / fmaxf(g_deg_p[n], 1.f) + pb[o];
    float q = g_accn[t] / fmaxf(g_deg_n[n], 1.f) + nb[o];
    out[t] = fmaxf(p, q);
}

// ---------------------------------------------------------------------------
extern "C" void kernel_launch(void* const* d_in, const int* in_sizes, int n_in,
                              void* d_out, int out_size) {
    const float* node_feat = (const float*)d_in[0];
    const float* net_feat  = (const float*)d_in[1];
    const float* pin_feat  = (const float*)d_in[2];
    const float* edge_feat = (const float*)d_in[3];
    const float* topo_w    = (const float*)d_in[4];
    const float* topo_b    = (const float*)d_in[5];
    const float* geom_w    = (const float*)d_in[6];
    const float* geom_b    = (const float*)d_in[7];
    const float* gc_w      = (const float*)d_in[8];
    const float* gc_b      = (const float*)d_in[9];
    const float* pinned_b  = (const float*)d_in[10];
    const float* near_b    = (const float*)d_in[11];
    const int* pins_src    = (const int*)d_in[12];
    const int* pins_dst    = (const int*)d_in[13];
    const int* pinned_src  = (const int*)d_in[14];
    const int* pinned_dst  = (const int*)d_in[15];
    const int* near_src    = (const int*)d_in[16];
    const int* near_dst    = (const int*)d_in[17];
    float* out = (float*)d_out;

    const int smem = (WSZ + WROWS) * (int)sizeof(float);   // 69632 B
    cudaFuncSetAttribute(k_nnconv, cudaFuncAttributeMaxDynamicSharedMemorySize, smem);

    float *accp_ptr = nullptr, *accn_ptr = nullptr;
    cudaGetSymbolAddress((void**)&accp_ptr, g_accp);
    cudaGetSymbolAddress((void**)&accn_ptr, g_accn);

    k_zero<<<512, 256>>>();
    k_deg<<<(NEDGE + 255) / 256, 256>>>(pins_src, pins_dst, pinned_dst, near_dst);
    k_pins<<<(NEDGE * HD + 255) / 256, 256>>>(node_feat, pins_src, pins_dst);
    k_netout<<<(N_NET * HD + 255) / 256, 256>>>(gc_w, gc_b, out);

    int nb = (NEDGE + 255) / 256;
    k_nnconv<<<nb, 256, smem>>>(net_feat,  pin_feat,  topo_w, topo_b,
                                pinned_src, pinned_dst, accp_ptr);
    k_nnconv<<<nb, 256, smem>>>(node_feat, edge_feat, geom_w, geom_b,
                                near_src,  near_dst,  accn_ptr);

    k_final<<<(N_NODE * HD + 255) / 256, 256>>>(pinned_b, near_b, out);
}